// round 14
// baseline (speedup 1.0000x reference)
#include <cuda_runtime.h>
#include <cuda_fp16.h>
#include <cstdint>

// ---------------- problem constants ----------------
#define BATCH   2048
#define CSUB    256
#define KDIM    256
#define NDIM    256
#define MTILE   64
#define CHUNK_K 64
#define NCH     4            // chunks per layer (256/64)

#define HSB     528          // row stride BYTES for A and B tiles (132 words = 4 mod 32)

#define A_OFF     0
#define A_BYTES   (MTILE * HSB)          // 33792
#define B_OFF     A_BYTES
#define B_BYTES   (CHUNK_K * HSB)        // 33792 per buffer (x2)
#define BIAS1_OFF (B_OFF + 2 * B_BYTES)  // 101376
#define BIAS2_OFF (BIAS1_OFF + 1024)
#define W3_OFF    (BIAS2_OFF + 1024)
#define RS_OFF    (W3_OFF + 1024)
#define SMEM_BYTES (RS_OFF + 256)        // 104704 -> 2 CTAs/SM

// ---------------- scratch (pre-converted fp16 operands) ----------------
__device__ __half g_W1h[CSUB * KDIM * NDIM];   // 32 MiB
__device__ __half g_W2h[CSUB * KDIM * NDIM];   // 32 MiB
__device__ __half g_xh[BATCH * KDIM];          // 1 MiB

// ---------------- helpers ----------------
__device__ __forceinline__ uint32_t smem_u32(const void* p) {
    uint32_t a;
    asm("{ .reg .u64 t; cvta.to.shared.u64 t, %1; cvt.u32.u64 %0, t; }" : "=r"(a) : "l"(p));
    return a;
}

__device__ __forceinline__ void cp16(uint32_t dst, const void* src) {
    asm volatile("cp.async.cg.shared.global [%0], [%1], 16;" :: "r"(dst), "l"(src) : "memory");
}
#define CP_COMMIT() asm volatile("cp.async.commit_group;" ::: "memory")
#define CP_WAIT0()  asm volatile("cp.async.wait_group 0;"  ::: "memory")

__device__ __forceinline__ void ldsm_x4(uint32_t* r, uint32_t addr) {
    asm volatile("ldmatrix.sync.aligned.m8n8.x4.shared.b16 {%0,%1,%2,%3}, [%4];"
                 : "=r"(r[0]), "=r"(r[1]), "=r"(r[2]), "=r"(r[3]) : "r"(addr));
}
__device__ __forceinline__ void ldsm_x4_t(uint32_t* r, uint32_t addr) {
    asm volatile("ldmatrix.sync.aligned.m8n8.x4.trans.shared.b16 {%0,%1,%2,%3}, [%4];"
                 : "=r"(r[0]), "=r"(r[1]), "=r"(r[2]), "=r"(r[3]) : "r"(addr));
}

__device__ __forceinline__ void mma_f16(float* d, const uint32_t* a,
                                        uint32_t b0, uint32_t b1) {
    asm volatile(
        "mma.sync.aligned.m16n8k16.row.col.f32.f16.f16.f32 "
        "{%0,%1,%2,%3}, {%4,%5,%6,%7}, {%8,%9}, {%0,%1,%2,%3};"
        : "+f"(d[0]), "+f"(d[1]), "+f"(d[2]), "+f"(d[3])
        : "r"(a[0]), "r"(a[1]), "r"(a[2]), "r"(a[3]), "r"(b0), "r"(b1));
}

// ---------------- prepass: f32 -> fp16 (rn), elementwise ----------------
__global__ void to_fp16_kernel(const float* __restrict__ src, int sel, int n4) {
    __half* dst = (sel == 0) ? g_W1h : (sel == 1) ? g_W2h : g_xh;
    int i = blockIdx.x * blockDim.x + threadIdx.x;
    const int stride = gridDim.x * blockDim.x;
    for (; i < n4; i += stride) {
        float4 v = reinterpret_cast<const float4*>(src)[i];
        __half2 h0 = __floats2half2_rn(v.x, v.y);
        __half2 h1 = __floats2half2_rn(v.z, v.w);
        uint2 o;
        o.x = reinterpret_cast<uint32_t&>(h0);
        o.y = reinterpret_cast<uint32_t&>(h1);
        reinterpret_cast<uint2*>(dst)[i] = o;
    }
}

// ---------------- staging: one 64k x 256n fp16 W chunk (512 threads) ----------------
__device__ __forceinline__ void stage_B(uint32_t base, const __half* src, int tid) {
    #pragma unroll
    for (int i = 0; i < 4; ++i) {
        const int u  = tid + i * 512;       // 2048 units = 64 rows x 32 x 16B
        const int k  = u >> 5;
        const int un = u & 31;
        cp16(base + k * HSB + un * 16, src + k * NDIM + un * 8);
    }
    CP_COMMIT();
}

// ---------------- main kernel ----------------
__global__ __launch_bounds__(512, 2)
void rfprism_main(const float* __restrict__ b1,
                  const float* __restrict__ b2,
                  const float* __restrict__ W3,
                  const float* __restrict__ b3,
                  float* __restrict__ out) {
    extern __shared__ char smem[];
    const uint32_t sb = smem_u32(smem);
    float* sBias1 = (float*)(smem + BIAS1_OFF);
    float* sBias2 = (float*)(smem + BIAS2_OFF);
    float* sW3v   = (float*)(smem + W3_OFF);
    float* rowsum = (float*)(smem + RS_OFF);

    const int tid  = threadIdx.x;
    const int warp = tid >> 5;          // 0..15
    const int lane = tid & 31;
    const int c    = blockIdx.y;
    const int b0   = blockIdx.x * MTILE;
    const int wm   = warp >> 3;         // 0..1 (M)
    const int wn   = warp & 7;          // 0..7 (N), 32 cols each
    const int g    = lane >> 2;         // 0..7
    const int tig  = lane & 3;          // 0..3

    // ldmatrix lane offset (same structure for A tiles and B-trans tiles)
    const uint32_t lmoff =
        ((((lane >> 3) & 1) * 8) + (lane & 7)) * HSB + ((lane >> 4) & 1) * 16;
    const uint32_t Aw = sb + A_OFF + (wm * 32) * HSB + lmoff;        // A base per warp
    const uint32_t Bw = lmoff + (wn * 32) * 2;                       // B offset per warp

    // ---- prologue: stage A (x tile) + W1 chunk 0; load biases/W3 ----
    #pragma unroll
    for (int i = 0; i < 4; ++i) {
        const int u   = tid + i * 512;      // 0..2047: 64 rows x 32 units
        const int row = u >> 5;
        const int un  = u & 31;
        cp16(sb + A_OFF + row * HSB + un * 16,
             g_xh + (size_t)(b0 + row) * KDIM + un * 8);
    }
    CP_COMMIT();
    stage_B(sb + B_OFF, g_W1h + (size_t)c * (KDIM * NDIM), tid);

    if (tid < 64) {
        ((float4*)sBias1)[tid] = ((const float4*)(b1 + (size_t)c * 256))[tid];
    } else if (tid < 128) {
        ((float4*)sBias2)[tid - 64] = ((const float4*)(b2 + (size_t)c * 256))[tid - 64];
    } else if (tid < 192) {
        ((float4*)sW3v)[tid - 128] = ((const float4*)(W3 + (size_t)c * 256))[tid - 128];
    } else if (tid < 256) {
        rowsum[tid - 192] = 0.0f;
    }

    float acc[2][4][4];                 // warp tile 32x32: 32 regs
    #pragma unroll
    for (int m = 0; m < 2; ++m)
        #pragma unroll
        for (int t = 0; t < 4; ++t)
            #pragma unroll
            for (int r = 0; r < 4; ++r)
                acc[m][t][r] = 0.0f;

    // ---- mainloop: 8 chunks (4 per layer), ONE sync per chunk ----
    #pragma unroll 1
    for (int kk = 0; kk < 2 * NCH; ++kk) {
        CP_WAIT0();
        __syncthreads();    // chunk kk data visible; buffer (kk+1)&1 free everywhere

        // stage chunk kk+1 into the buffer freed at kk-1 (lands during compute)
        if (kk + 1 < 2 * NCH) {
            const int t2 = kk + 1;
            const __half* W = (t2 < NCH) ? g_W1h : g_W2h;
            stage_B(sb + B_OFF + (t2 & 1) * B_BYTES,
                    W + (size_t)c * (KDIM * NDIM) + (size_t)(t2 & (NCH - 1)) * (CHUNK_K * NDIM),
                    tid);
        }

        const uint32_t Bbase = sb + B_OFF + (kk & 1) * B_BYTES;
        const int kabase = (kk & (NCH - 1)) * CHUNK_K;

        #pragma unroll
        for (int s = 0; s < CHUNK_K / 16; ++s) {     // 4 k16 steps per chunk
            const int ka = kabase + s * 16;

            uint32_t bb[2][4];
            #pragma unroll
            for (int j = 0; j < 2; ++j)              // 2 n-tiles of 16 cols
                ldsm_x4_t(bb[j], Bbase + s * 16 * HSB + Bw + (j * 16) * 2);

            uint32_t a[2][4];
            #pragma unroll
            for (int m = 0; m < 2; ++m)
                ldsm_x4(a[m], Aw + m * 16 * HSB + ka * 2);

            #pragma unroll
            for (int m = 0; m < 2; ++m)
                #pragma unroll
                for (int t = 0; t < 4; ++t)
                    mma_f16(acc[m][t], a[m],
                            bb[t >> 1][(t & 1) * 2], bb[t >> 1][(t & 1) * 2 + 1]);
        }

        if (kk == NCH - 1) {
            __syncthreads();   // everyone done reading layer-1 A before overwrite
            // epilogue 1: A <- fp16(relu(acc + b1))
            #pragma unroll
            for (int m = 0; m < 2; ++m) {
                const int r0 = wm * 32 + m * 16 + g;
                const int r1 = r0 + 8;
                #pragma unroll
                for (int t = 0; t < 4; ++t) {
                    const int c0 = wn * 32 + t * 8 + 2 * tig;
                    float v00 = fmaxf(acc[m][t][0] + sBias1[c0],     0.0f);
                    float v01 = fmaxf(acc[m][t][1] + sBias1[c0 + 1], 0.0f);
                    float v10 = fmaxf(acc[m][t][2] + sBias1[c0],     0.0f);
                    float v11 = fmaxf(acc[m][t][3] + sBias1[c0 + 1], 0.0f);
                    __half2 h0 = __floats2half2_rn(v00, v01);
                    __half2 h1 = __floats2half2_rn(v10, v11);
                    *(uint32_t*)(smem + A_OFF + r0 * HSB + c0 * 2) =
                        reinterpret_cast<uint32_t&>(h0);
                    *(uint32_t*)(smem + A_OFF + r1 * HSB + c0 * 2) =
                        reinterpret_cast<uint32_t&>(h1);
                }
            }
            #pragma unroll
            for (int m = 0; m < 2; ++m)
                #pragma unroll
                for (int t = 0; t < 4; ++t)
                    #pragma unroll
                    for (int r = 0; r < 4; ++r)
                        acc[m][t][r] = 0.0f;
            // visibility for layer-2 reads: top-of-next-chunk __syncthreads
        }
    }

    // ---- epilogue 2 + layer 3: rowsum += relu(acc + b2) . W3 ----
    #pragma unroll
    for (int m = 0; m < 2; ++m) {
        const int r0 = wm * 32 + m * 16 + g;
        const int r1 = r0 + 8;
        float s0 = 0.0f, s1 = 0.0f;
        #pragma unroll
        for (int t = 0; t < 4; ++t) {
            const int c0 = wn * 32 + t * 8 + 2 * tig;
            const float w0 = sW3v[c0], w1 = sW3v[c0 + 1];
            const float bb0 = sBias2[c0], bb1 = sBias2[c0 + 1];
            s0 += fmaxf(acc[m][t][0] + bb0, 0.0f) * w0
                + fmaxf(acc[m][t][1] + bb1, 0.0f) * w1;
            s1 += fmaxf(acc[m][t][2] + bb0, 0.0f) * w0
                + fmaxf(acc[m][t][3] + bb1, 0.0f) * w1;
        }
        s0 += __shfl_xor_sync(0xffffffffu, s0, 1);
        s0 += __shfl_xor_sync(0xffffffffu, s0, 2);
        s1 += __shfl_xor_sync(0xffffffffu, s1, 1);
        s1 += __shfl_xor_sync(0xffffffffu, s1, 2);
        if (tig == 0) {
            atomicAdd(&rowsum[r0], s0);
            atomicAdd(&rowsum[r1], s1);
        }
    }

    __syncthreads();
    if (tid < MTILE)
        out[(size_t)(b0 + tid) * CSUB + c] = rowsum[tid] + b3[c];
}

extern "C" void kernel_launch(void* const* d_in, const int* in_sizes, int n_in,
                              void* d_out, int out_size) {
    (void)in_sizes; (void)n_in; (void)out_size;
    const float* x  = (const float*)d_in[0];
    const float* W1 = (const float*)d_in[1];
    const float* b1 = (const float*)d_in[2];
    const float* W2 = (const float*)d_in[3];
    const float* b2 = (const float*)d_in[4];
    const float* W3 = (const float*)d_in[5];
    const float* b3 = (const float*)d_in[6];
    float* out = (float*)d_out;

    // prepass: fp16-convert W1, W2, x into scratch
    const int nW4 = (CSUB * KDIM * NDIM) / 4;    // 4,194,304
    const int nX4 = (BATCH * KDIM) / 4;          // 131,072
    to_fp16_kernel<<<4096, 256>>>(W1, 0, nW4);
    to_fp16_kernel<<<4096, 256>>>(W2, 1, nW4);
    to_fp16_kernel<<<512, 256>>>(x,  2, nX4);

    cudaFuncSetAttribute(rfprism_main,
                         cudaFuncAttributeMaxDynamicSharedMemorySize, SMEM_BYTES);
    dim3 grid(BATCH / MTILE, CSUB);   // (32, 256)
    rfprism_main<<<grid, 512, SMEM_BYTES>>>(b1, b2, W3, b3, out);
}

// round 15
// speedup vs baseline: 1.0045x; 1.0045x over previous
#include <cuda_runtime.h>
#include <cuda_fp16.h>
#include <cstdint>

// ---------------- problem constants ----------------
#define BATCH   2048
#define CSUB    256
#define KDIM    256
#define NDIM    256
#define G       4                    // batch groups -> grid.x
#define BT_PER  (BATCH / (G * 64))   // 8 batch-tiles of 64 rows per CTA

#define HSB     528                  // row stride BYTES (132 words = 4 mod 32, conflict-free)

// ---- SMEM layout (shared by K1/K2) ----
#define W_OFF    0
#define W_BYTES  (256 * HSB)                 // 135168: resident W[c] (256k x 256n)
#define X_OFF    W_BYTES
#define XBUF     (64 * HSB)                  // 33792 per x/h1 tile buffer (x2)
#define BIAS_OFF (X_OFF + 2 * XBUF)          // 202752
#define W3S_OFF  (BIAS_OFF + 1024)           // 203776 (K2 only)
#define RS_OFF   (W3S_OFF + 1024)            // 204800: rowsum[64][8] (K2 only)
#define SMEM_K1  (BIAS_OFF + 1024)           // 203776
#define SMEM_K2  (RS_OFF + 2048)             // 206848

// ---------------- scratch ----------------
__device__ __half g_W1h[CSUB * KDIM * NDIM];       // 32 MiB
__device__ __half g_W2h[CSUB * KDIM * NDIM];       // 32 MiB
__device__ __half g_xh[BATCH * KDIM];              // 1 MiB
__device__ __half g_h1[(size_t)CSUB * BATCH * NDIM]; // 256 MiB intermediate

// ---------------- helpers ----------------
__device__ __forceinline__ uint32_t smem_u32(const void* p) {
    uint32_t a;
    asm("{ .reg .u64 t; cvta.to.shared.u64 t, %1; cvt.u32.u64 %0, t; }" : "=r"(a) : "l"(p));
    return a;
}

__device__ __forceinline__ void cp16(uint32_t dst, const void* src) {
    asm volatile("cp.async.cg.shared.global [%0], [%1], 16;" :: "r"(dst), "l"(src) : "memory");
}
#define CP_COMMIT() asm volatile("cp.async.commit_group;" ::: "memory")
#define CP_WAIT0()  asm volatile("cp.async.wait_group 0;"  ::: "memory")

__device__ __forceinline__ void ldsm_x4(uint32_t* r, uint32_t addr) {
    asm volatile("ldmatrix.sync.aligned.m8n8.x4.shared.b16 {%0,%1,%2,%3}, [%4];"
                 : "=r"(r[0]), "=r"(r[1]), "=r"(r[2]), "=r"(r[3]) : "r"(addr));
}
__device__ __forceinline__ void ldsm_x4_t(uint32_t* r, uint32_t addr) {
    asm volatile("ldmatrix.sync.aligned.m8n8.x4.trans.shared.b16 {%0,%1,%2,%3}, [%4];"
                 : "=r"(r[0]), "=r"(r[1]), "=r"(r[2]), "=r"(r[3]) : "r"(addr));
}

__device__ __forceinline__ void mma_f16(float* d, const uint32_t* a,
                                        uint32_t b0, uint32_t b1) {
    asm volatile(
        "mma.sync.aligned.m16n8k16.row.col.f32.f16.f16.f32 "
        "{%0,%1,%2,%3}, {%4,%5,%6,%7}, {%8,%9}, {%0,%1,%2,%3};"
        : "+f"(d[0]), "+f"(d[1]), "+f"(d[2]), "+f"(d[3])
        : "r"(a[0]), "r"(a[1]), "r"(a[2]), "r"(a[3]), "r"(b0), "r"(b1));
}

// ---------------- prepass: f32 -> fp16 (rn), elementwise ----------------
__global__ void to_fp16_kernel(const float* __restrict__ src, int sel, int n4) {
    __half* dst = (sel == 0) ? g_W1h : (sel == 1) ? g_W2h : g_xh;
    int i = blockIdx.x * blockDim.x + threadIdx.x;
    const int stride = gridDim.x * blockDim.x;
    for (; i < n4; i += stride) {
        float4 v = reinterpret_cast<const float4*>(src)[i];
        __half2 h0 = __floats2half2_rn(v.x, v.y);
        __half2 h1 = __floats2half2_rn(v.z, v.w);
        uint2 o;
        o.x = reinterpret_cast<uint32_t&>(h0);
        o.y = reinterpret_cast<uint32_t&>(h1);
        reinterpret_cast<uint2*>(dst)[i] = o;
    }
}

// stage one 64-row x 256-col fp16 tile (2048 16B units, 512 threads)
__device__ __forceinline__ void stage_tile64(uint32_t base, const __half* src, int tid) {
    #pragma unroll
    for (int i = 0; i < 4; ++i) {
        const int u   = tid + i * 512;
        const int row = u >> 5;
        const int un  = u & 31;
        cp16(base + row * HSB + un * 16, src + row * 256 + un * 8);
    }
    CP_COMMIT();
}

// stage resident W[c]: 256 rows x 256 cols (8192 units)
__device__ __forceinline__ void stage_W(uint32_t base, const __half* src, int tid) {
    #pragma unroll
    for (int i = 0; i < 16; ++i) {
        const int u  = tid + i * 512;
        const int k  = u >> 5;
        const int un = u & 31;
        cp16(base + k * HSB + un * 16, src + k * 256 + un * 8);
    }
    CP_COMMIT();
}

// ======================= K1: h1 = relu(x @ W1[c] + b1) =======================
__global__ __launch_bounds__(512, 1)
void rfprism_k1(const float* __restrict__ b1) {
    extern __shared__ char smem[];
    const uint32_t sb = smem_u32(smem);
    float* sBias = (float*)(smem + BIAS_OFF);

    const int tid  = threadIdx.x;
    const int warp = tid >> 5;
    const int lane = tid & 31;
    const int c    = blockIdx.y;
    const int bg0  = blockIdx.x * (BT_PER * 64);
    const int wm   = warp >> 3;   // 0..1
    const int wn   = warp & 7;    // 0..7 (32 cols each)
    const int g    = lane >> 2;
    const int tig  = lane & 3;

    const uint32_t lmoff =
        ((((lane >> 3) & 1) * 8) + (lane & 7)) * HSB + ((lane >> 4) & 1) * 16;
    const uint32_t Bw = sb + W_OFF + lmoff + (wn * 32) * 2;

    stage_W(sb + W_OFF, g_W1h + ((size_t)c << 16), tid);
    stage_tile64(sb + X_OFF, g_xh + (size_t)bg0 * 256, tid);
    if (tid < 64)
        ((float4*)sBias)[tid] = ((const float4*)(b1 + (size_t)c * 256))[tid];

    float acc[2][4][4];
    #pragma unroll
    for (int m = 0; m < 2; ++m)
        #pragma unroll
        for (int t = 0; t < 4; ++t)
            #pragma unroll
            for (int r = 0; r < 4; ++r) acc[m][t][r] = 0.0f;

    #pragma unroll 1
    for (int bt = 0; bt < BT_PER; ++bt) {
        CP_WAIT0();
        __syncthreads();   // W + x(bt) visible; buffer (bt+1)&1 free (compute bt-1 done)

        if (bt + 1 < BT_PER)
            stage_tile64(sb + X_OFF + ((bt + 1) & 1) * XBUF,
                         g_xh + (size_t)(bg0 + (bt + 1) * 64) * 256, tid);

        const uint32_t Aw = sb + X_OFF + (bt & 1) * XBUF + (wm * 32) * HSB + lmoff;

        #pragma unroll
        for (int s = 0; s < 16; ++s) {
            uint32_t bb[2][4];
            #pragma unroll
            for (int j = 0; j < 2; ++j)
                ldsm_x4_t(bb[j], Bw + s * 16 * HSB + (j * 16) * 2);
            uint32_t a[2][4];
            #pragma unroll
            for (int m = 0; m < 2; ++m)
                ldsm_x4(a[m], Aw + m * 16 * HSB + s * 32);
            #pragma unroll
            for (int m = 0; m < 2; ++m)
                #pragma unroll
                for (int t = 0; t < 4; ++t)
                    mma_f16(acc[m][t], a[m],
                            bb[t >> 1][(t & 1) * 2], bb[t >> 1][(t & 1) * 2 + 1]);
        }

        // epilogue: h1 = fp16(relu(acc + b1)) -> gmem (registers only, no sync)
        const size_t rowbase = (size_t)c * BATCH + bg0 + bt * 64;
        #pragma unroll
        for (int m = 0; m < 2; ++m) {
            const int r0 = wm * 32 + m * 16 + g;
            const int r1 = r0 + 8;
            #pragma unroll
            for (int t = 0; t < 4; ++t) {
                const int c0 = wn * 32 + t * 8 + 2 * tig;
                float v00 = fmaxf(acc[m][t][0] + sBias[c0],     0.0f);
                float v01 = fmaxf(acc[m][t][1] + sBias[c0 + 1], 0.0f);
                float v10 = fmaxf(acc[m][t][2] + sBias[c0],     0.0f);
                float v11 = fmaxf(acc[m][t][3] + sBias[c0 + 1], 0.0f);
                __half2 h0 = __floats2half2_rn(v00, v01);
                __half2 h1v = __floats2half2_rn(v10, v11);
                *(uint32_t*)(g_h1 + (rowbase + r0) * 256 + c0) =
                    reinterpret_cast<uint32_t&>(h0);
                *(uint32_t*)(g_h1 + (rowbase + r1) * 256 + c0) =
                    reinterpret_cast<uint32_t&>(h1v);
                acc[m][t][0] = acc[m][t][1] = acc[m][t][2] = acc[m][t][3] = 0.0f;
            }
        }
    }
}

// ========== K2: out[b][c] = relu(h1 @ W2[c] + b2) . W3[c] + b3[c] ==========
__global__ __launch_bounds__(512, 1)
void rfprism_k2(const float* __restrict__ b2,
                const float* __restrict__ W3,
                const float* __restrict__ b3,
                float* __restrict__ out) {
    extern __shared__ char smem[];
    const uint32_t sb = smem_u32(smem);
    float* sBias  = (float*)(smem + BIAS_OFF);
    float* sW3v   = (float*)(smem + W3S_OFF);
    float* rowsum = (float*)(smem + RS_OFF);    // [64][8]

    const int tid  = threadIdx.x;
    const int warp = tid >> 5;
    const int lane = tid & 31;
    const int c    = blockIdx.y;
    const int bg0  = blockIdx.x * (BT_PER * 64);
    const int wm   = warp >> 3;
    const int wn   = warp & 7;
    const int g    = lane >> 2;
    const int tig  = lane & 3;

    const uint32_t lmoff =
        ((((lane >> 3) & 1) * 8) + (lane & 7)) * HSB + ((lane >> 4) & 1) * 16;
    const uint32_t Bw = sb + W_OFF + lmoff + (wn * 32) * 2;

    stage_W(sb + W_OFF, g_W2h + ((size_t)c << 16), tid);
    stage_tile64(sb + X_OFF, g_h1 + ((size_t)c * BATCH + bg0) * 256, tid);
    if (tid < 64) {
        ((float4*)sBias)[tid] = ((const float4*)(b2 + (size_t)c * 256))[tid];
    } else if (tid < 128) {
        ((float4*)sW3v)[tid - 64] = ((const float4*)(W3 + (size_t)c * 256))[tid - 64];
    }
    const float b3c = __ldg(b3 + c);

    float acc[2][4][4];
    #pragma unroll
    for (int m = 0; m < 2; ++m)
        #pragma unroll
        for (int t = 0; t < 4; ++t)
            #pragma unroll
            for (int r = 0; r < 4; ++r) acc[m][t][r] = 0.0f;

    #pragma unroll 1
    for (int bt = 0; bt < BT_PER; ++bt) {
        CP_WAIT0();
        __syncthreads();

        if (bt + 1 < BT_PER)
            stage_tile64(sb + X_OFF + ((bt + 1) & 1) * XBUF,
                         g_h1 + ((size_t)c * BATCH + bg0 + (bt + 1) * 64) * 256, tid);

        const uint32_t Aw = sb + X_OFF + (bt & 1) * XBUF + (wm * 32) * HSB + lmoff;

        #pragma unroll
        for (int s = 0; s < 16; ++s) {
            uint32_t bb[2][4];
            #pragma unroll
            for (int j = 0; j < 2; ++j)
                ldsm_x4_t(bb[j], Bw + s * 16 * HSB + (j * 16) * 2);
            uint32_t a[2][4];
            #pragma unroll
            for (int m = 0; m < 2; ++m)
                ldsm_x4(a[m], Aw + m * 16 * HSB + s * 32);
            #pragma unroll
            for (int m = 0; m < 2; ++m)
                #pragma unroll
                for (int t = 0; t < 4; ++t)
                    mma_f16(acc[m][t], a[m],
                            bb[t >> 1][(t & 1) * 2], bb[t >> 1][(t & 1) * 2 + 1]);
        }

        // epilogue: partial dot with W3, per-warp slot (no atomics)
        #pragma unroll
        for (int m = 0; m < 2; ++m) {
            const int r0 = wm * 32 + m * 16 + g;
            const int r1 = r0 + 8;
            float s0 = 0.0f, s1 = 0.0f;
            #pragma unroll
            for (int t = 0; t < 4; ++t) {
                const int c0 = wn * 32 + t * 8 + 2 * tig;
                const float w0 = sW3v[c0], w1 = sW3v[c0 + 1];
                const float bb0 = sBias[c0], bb1 = sBias[c0 + 1];
                s0 += fmaxf(acc[m][t][0] + bb0, 0.0f) * w0
                    + fmaxf(acc[m][t][1] + bb1, 0.0f) * w1;
                s1 += fmaxf(acc[m][t][2] + bb0, 0.0f) * w0
                    + fmaxf(acc[m][t][3] + bb1, 0.0f) * w1;
                acc[m][t][0] = acc[m][t][1] = acc[m][t][2] = acc[m][t][3] = 0.0f;
            }
            s0 += __shfl_xor_sync(0xffffffffu, s0, 1);
            s0 += __shfl_xor_sync(0xffffffffu, s0, 2);
            s1 += __shfl_xor_sync(0xffffffffu, s1, 1);
            s1 += __shfl_xor_sync(0xffffffffu, s1, 2);
            if (tig == 0) {
                rowsum[r0 * 8 + wn] = s0;
                rowsum[r1 * 8 + wn] = s1;
            }
        }
        __syncthreads();
        if (tid < 64) {
            float4 p = ((const float4*)rowsum)[tid * 2];
            float4 q = ((const float4*)rowsum)[tid * 2 + 1];
            float s = (p.x + p.y) + (p.z + p.w) + (q.x + q.y) + (q.z + q.w) + b3c;
            out[(size_t)(bg0 + bt * 64 + tid) * CSUB + c] = s;
        }
    }
}

extern "C" void kernel_launch(void* const* d_in, const int* in_sizes, int n_in,
                              void* d_out, int out_size) {
    (void)in_sizes; (void)n_in; (void)out_size;
    const float* x  = (const float*)d_in[0];
    const float* W1 = (const float*)d_in[1];
    const float* b1 = (const float*)d_in[2];
    const float* W2 = (const float*)d_in[3];
    const float* b2 = (const float*)d_in[4];
    const float* W3 = (const float*)d_in[5];
    const float* b3 = (const float*)d_in[6];
    float* out = (float*)d_out;

    const int nW4 = (CSUB * KDIM * NDIM) / 4;
    const int nX4 = (BATCH * KDIM) / 4;
    to_fp16_kernel<<<4096, 256>>>(W1, 0, nW4);
    to_fp16_kernel<<<4096, 256>>>(W2, 1, nW4);
    to_fp16_kernel<<<512, 256>>>(x,  2, nX4);

    cudaFuncSetAttribute(rfprism_k1,
                         cudaFuncAttributeMaxDynamicSharedMemorySize, SMEM_K1);
    cudaFuncSetAttribute(rfprism_k2,
                         cudaFuncAttributeMaxDynamicSharedMemorySize, SMEM_K2);

    dim3 grid(G, CSUB);    // (4, 256) = 1024 CTAs each
    rfprism_k1<<<grid, 512, SMEM_K1>>>(b1);
    rfprism_k2<<<grid, 512, SMEM_K2>>>(b2, W3, b3, out);
}